// round 9
// baseline (speedup 1.0000x reference)
#include <cuda_runtime.h>
#include <math.h>
#include <stdint.h>

#define DD 256
#define MC 50
#define NPATH 65536
#define NTOK 65586
#define LDQ 768
#define ATT_SCALE 0.0625f

// ---------------- packed fp32x2 helpers (Blackwell FFMA2) ------------------
__device__ __forceinline__ void fma2(uint64_t& d, uint64_t a, uint64_t b) {
    asm("fma.rn.f32x2 %0, %1, %2, %0;" : "+l"(d) : "l"(a), "l"(b));
}
__device__ __forceinline__ uint64_t splat2(float x) {
    uint64_t r; asm("mov.b64 %0, {%1, %1};" : "=l"(r) : "f"(x)); return r;
}
__device__ __forceinline__ float2 unpack2(uint64_t v) {
    float2 r; asm("mov.b64 {%0, %1}, %2;" : "=f"(r.x), "=f"(r.y) : "l"(v)); return r;
}

// ---------------- scratch (device globals; no allocation allowed) ----------
__device__ float g_QKV[(size_t)NTOK * LDQ];
__device__ float g_S2[(size_t)MC * NPATH];
__device__ float g_P[(size_t)NPATH * 64];
__device__ float g_OCC[MC * DD];
__device__ float g_OSC[MC * DD];
__device__ float g_SS[MC * 52];
__device__ float g_QL[(size_t)NPATH * DD];
__device__ float g_KL[(size_t)NPATH * DD];
__device__ float g_KSUM[DD];
__device__ float g_KV[DD * DD];
__device__ float g_ZFAC[NPATH];
__device__ float g_FM[(size_t)NPATH * DD];
__device__ float g_TMP[(size_t)NPATH * DD];
__device__ float g_Acc[MC], g_Asc[MC];
__device__ float g_Acp[NPATH], g_Asp[NPATH];
__device__ float g_rowM[MC], g_rowIL[MC];
__device__ float g_ST[2];
__device__ float g_SP[DD];
__device__ float g_H4[4 * DD];
__device__ float g_Wfa[DD * DD], g_Wfb[DD * DD], g_WfW2[DD * DD];
__device__ float g_bfa[DD], g_bfb[DD], g_b2p[DD];
__device__ float g_VaP[64 * DD], g_VbP[64 * DD], g_VW2[64 * DD];

// ---------------- zero accumulators ---------------------------------------
__global__ void zerok() {
    int id = blockIdx.x * 256 + threadIdx.x;
    if (id < NPATH) { g_Acp[id] = 0.f; g_Asp[id] = 0.f; }
    if (id < MC * DD) g_OCC[id] = 0.f;
    if (id < DD * DD) g_KV[id] = 0.f;
    if (id < DD) g_KSUM[id] = 0.f;
    if (id < MC) { g_Acc[id] = 0.f; g_Asc[id] = 0.f; }
    if (id < 4 * DD) g_H4[id] = 0.f;
    if (id < 64 * DD) { g_VaP[id] = 0.f; g_VbP[id] = 0.f; g_VW2[id] = 0.f; }
}

// ---------------- double-buffered SGEMM with f32x2 inner loop --------------
#define GEMM_COMPUTE(BUF)                                                    \
    _Pragma("unroll")                                                        \
    for (int kk = 0; kk < 8; kk++) {                                         \
        float a[8];                                                          \
        *(float4*)&a[0] = *(const float4*)&As[BUF][kk][ty * 8];              \
        *(float4*)&a[4] = *(const float4*)&As[BUF][kk][ty * 8 + 4];          \
        uint64_t bp[4];                                                      \
        bp[0] = *(const uint64_t*)&Bs[BUF][kk][tx * 8];                      \
        bp[1] = *(const uint64_t*)&Bs[BUF][kk][tx * 8 + 2];                  \
        bp[2] = *(const uint64_t*)&Bs[BUF][kk][tx * 8 + 4];                  \
        bp[3] = *(const uint64_t*)&Bs[BUF][kk][tx * 8 + 6];                  \
        _Pragma("unroll")                                                    \
        for (int i = 0; i < 8; i++) {                                        \
            uint64_t aa = splat2(a[i]);                                      \
            _Pragma("unroll")                                                \
            for (int j = 0; j < 4; j++) fma2(acc[i][j], aa, bp[j]);          \
        }                                                                    \
    }

__global__ __launch_bounds__(256, 2)
void sgemm_db(const float* __restrict__ A, int lda,
              const float* __restrict__ B, int ldb,
              float* __restrict__ C, int ldc,
              int M, int K,
              const float* __restrict__ bias,
              const float* __restrict__ rowscale,
              const float* __restrict__ addend, int addld)
{
    __shared__ float As[2][8][128];
    __shared__ float Bs[2][8][128];
    const int t = threadIdx.x;
    const int row0 = blockIdx.y * 128;
    const int col0 = blockIdx.x * 128;
    const int tx = t & 15, ty = t >> 4;
    const int arow = t >> 1, acol = (t & 1) * 4;
    const int brow = t >> 5, bcol = (t & 31) * 4;
    const bool aval = (row0 + arow < M);
    const float* Aptr = A + (size_t)(row0 + arow) * lda + acol;
    const float* Bptr = B + (size_t)brow * ldb + col0 + bcol;

    uint64_t acc[8][4];
#pragma unroll
    for (int i = 0; i < 8; i++)
#pragma unroll
        for (int j = 0; j < 4; j++) acc[i][j] = 0ull;

    float4 av = aval ? *(const float4*)Aptr : make_float4(0.f, 0.f, 0.f, 0.f);
    float4 bv = *(const float4*)Bptr;
    As[0][acol + 0][arow] = av.x; As[0][acol + 1][arow] = av.y;
    As[0][acol + 2][arow] = av.z; As[0][acol + 3][arow] = av.w;
    *(float4*)&Bs[0][brow][bcol] = bv;
    __syncthreads();

    int buf = 0;
    for (int k0 = 8; k0 < K; k0 += 8) {
        av = aval ? *(const float4*)(Aptr + k0) : make_float4(0.f, 0.f, 0.f, 0.f);
        bv = *(const float4*)(Bptr + (size_t)k0 * ldb);
        GEMM_COMPUTE(buf)
        int nb = buf ^ 1;
        As[nb][acol + 0][arow] = av.x; As[nb][acol + 1][arow] = av.y;
        As[nb][acol + 2][arow] = av.z; As[nb][acol + 3][arow] = av.w;
        *(float4*)&Bs[nb][brow][bcol] = bv;
        __syncthreads();
        buf = nb;
    }
    GEMM_COMPUTE(buf)

#pragma unroll
    for (int i = 0; i < 8; i++) {
        int r = row0 + ty * 8 + i;
        if (r >= M) continue;
        float rs = rowscale ? rowscale[r] : 1.f;
#pragma unroll
        for (int j = 0; j < 4; j++) {
            int c = col0 + tx * 8 + j * 2;
            float2 v = unpack2(acc[i][j]);
            v.x *= rs; v.y *= rs;
            if (bias) { v.x += bias[c]; v.y += bias[c + 1]; }
            if (addend) {
                v.x += addend[(size_t)r * addld + c];
                v.y += addend[(size_t)r * addld + c + 1];
            }
            C[(size_t)r * ldc + c] = v.x;
            C[(size_t)r * ldc + c + 1] = v.y;
        }
    }
}

// ---------------- small-matrix SGEMM: 64x64 tiles, 4x4 micro ---------------
__global__ __launch_bounds__(256, 4)
void sgemm_small(const float* __restrict__ A, int lda,
                 const float* __restrict__ B, int ldb,
                 float* __restrict__ C, int ldc, int M, int K)
{
    __shared__ float As[16][64];
    __shared__ float Bs[16][68];
    const int t = threadIdx.x;
    const int row0 = blockIdx.y * 64, col0 = blockIdx.x * 64;
    const int tx = t & 15, ty = t >> 4;
    const int arow = t >> 2, acol = (t & 3) * 4;
    const int brow = t >> 4, bcol = (t & 15) * 4;
    float acc[4][4];
#pragma unroll
    for (int i = 0; i < 4; i++)
#pragma unroll
        for (int j = 0; j < 4; j++) acc[i][j] = 0.f;

    for (int k0 = 0; k0 < K; k0 += 16) {
        float4 av = make_float4(0.f, 0.f, 0.f, 0.f);
        if (row0 + arow < M)
            av = *(const float4*)(A + (size_t)(row0 + arow) * lda + k0 + acol);
        As[acol + 0][arow] = av.x; As[acol + 1][arow] = av.y;
        As[acol + 2][arow] = av.z; As[acol + 3][arow] = av.w;
        *(float4*)&Bs[brow][bcol] =
            *(const float4*)(B + (size_t)(k0 + brow) * ldb + col0 + bcol);
        __syncthreads();
#pragma unroll
        for (int kk = 0; kk < 16; kk++) {
            float a[4], b[4];
            *(float4*)a = *(const float4*)&As[kk][ty * 4];
            *(float4*)b = *(const float4*)&Bs[kk][tx * 4];
#pragma unroll
            for (int i = 0; i < 4; i++)
#pragma unroll
                for (int j = 0; j < 4; j++)
                    acc[i][j] = fmaf(a[i], b[j], acc[i][j]);
        }
        __syncthreads();
    }
#pragma unroll
    for (int i = 0; i < 4; i++) {
        int r = row0 + ty * 4 + i;
        if (r >= M) continue;
#pragma unroll
        for (int j = 0; j < 4; j++)
            C[(size_t)r * ldc + col0 + tx * 4 + j] = acc[i][j];
    }
}

// ---------------- bias fold: out = base + vvec @ Wm ------------------------
__global__ void biasfold(const float* __restrict__ base, const float* __restrict__ vvec,
                         const float* __restrict__ Wm, float* __restrict__ out)
{
    int c = threadIdx.x;
    float s = base[c];
    for (int k = 0; k < DD; k++) s = fmaf(vvec[k], Wm[k * DD + c], s);
    out[c] = s;
}

// ---------------- dual-GEMM gated branch (f32x2, double-buffered) ----------
#define DG_COMPUTE(BUF)                                                      \
    _Pragma("unroll")                                                        \
    for (int kk = 0; kk < 8; kk++) {                                         \
        float a[8];                                                          \
        *(float4*)&a[0] = *(const float4*)&As[BUF][kk][ty * 8];              \
        *(float4*)&a[4] = *(const float4*)&As[BUF][kk][ty * 8 + 4];          \
        uint64_t b1p[2], b2p_[2];                                            \
        b1p[0] = *(const uint64_t*)&B1s[BUF][kk][tx * 4];                    \
        b1p[1] = *(const uint64_t*)&B1s[BUF][kk][tx * 4 + 2];                \
        b2p_[0] = *(const uint64_t*)&B2s[BUF][kk][tx * 4];                   \
        b2p_[1] = *(const uint64_t*)&B2s[BUF][kk][tx * 4 + 2];               \
        _Pragma("unroll")                                                    \
        for (int i = 0; i < 8; i++) {                                        \
            uint64_t aa = splat2(a[i]);                                      \
            fma2(acc1[i][0], aa, b1p[0]); fma2(acc1[i][1], aa, b1p[1]);      \
            fma2(acc2[i][0], aa, b2p_[0]); fma2(acc2[i][1], aa, b2p_[1]);    \
        }                                                                    \
    }

__global__ __launch_bounds__(256, 2)
void dualgated(const float* __restrict__ A, int lda, int M, int K,
               const float* __restrict__ W1m, const float* __restrict__ b1v,
               const float* __restrict__ W2m, const float* __restrict__ b2v,
               const float* __restrict__ Wc, const float* __restrict__ bcp,
               float* __restrict__ Avec)
{
    __shared__ float As[2][8][128];
    __shared__ float B1s[2][8][64];
    __shared__ float B2s[2][8][64];
    __shared__ float red[128][17];
    const int t = threadIdx.x;
    const int row0 = blockIdx.y * 128;
    const int col0 = blockIdx.x * 64;
    const int tx = t & 15, ty = t >> 4;
    const int arow = t >> 1, acol = (t & 1) * 4;
    const int u = t & 127;
    const int br = u >> 4, bc4 = (u & 15) * 4;
    const bool isb1 = (t < 128);
    const bool aval = (row0 + arow < M);
    const float* Aptr = A + (size_t)(row0 + arow) * lda + acol;
    const float* Bptr = (isb1 ? W1m : W2m) + (size_t)br * DD + col0 + bc4;

    uint64_t acc1[8][2], acc2[8][2];
#pragma unroll
    for (int i = 0; i < 8; i++) {
        acc1[i][0] = acc1[i][1] = 0ull;
        acc2[i][0] = acc2[i][1] = 0ull;
    }

    float4 av = aval ? *(const float4*)Aptr : make_float4(0.f, 0.f, 0.f, 0.f);
    float4 bv = *(const float4*)Bptr;
    As[0][acol + 0][arow] = av.x; As[0][acol + 1][arow] = av.y;
    As[0][acol + 2][arow] = av.z; As[0][acol + 3][arow] = av.w;
    if (isb1) *(float4*)&B1s[0][br][bc4] = bv;
    else      *(float4*)&B2s[0][br][bc4] = bv;
    __syncthreads();

    int buf = 0;
    for (int k0 = 8; k0 < K; k0 += 8) {
        av = aval ? *(const float4*)(Aptr + k0) : make_float4(0.f, 0.f, 0.f, 0.f);
        bv = *(const float4*)(Bptr + (size_t)k0 * DD);
        DG_COMPUTE(buf)
        int nb = buf ^ 1;
        As[nb][acol + 0][arow] = av.x; As[nb][acol + 1][arow] = av.y;
        As[nb][acol + 2][arow] = av.z; As[nb][acol + 3][arow] = av.w;
        if (isb1) *(float4*)&B1s[nb][br][bc4] = bv;
        else      *(float4*)&B2s[nb][br][bc4] = bv;
        __syncthreads();
        buf = nb;
    }
    DG_COMPUTE(buf)

    float wc[4], bav[4], bbv[4];
#pragma unroll
    for (int j = 0; j < 4; j++) {
        int c = col0 + tx * 4 + j;
        wc[j] = Wc[c]; bav[j] = b1v[c]; bbv[j] = b2v[c];
    }
#pragma unroll
    for (int i = 0; i < 8; i++) {
        float a1[4], a2[4];
        float2 p;
        p = unpack2(acc1[i][0]); a1[0] = p.x; a1[1] = p.y;
        p = unpack2(acc1[i][1]); a1[2] = p.x; a1[3] = p.y;
        p = unpack2(acc2[i][0]); a2[0] = p.x; a2[1] = p.y;
        p = unpack2(acc2[i][1]); a2[2] = p.x; a2[3] = p.y;
        float s = 0.f;
#pragma unroll
        for (int j = 0; j < 4; j++) {
            float ya = __tanhf(a1[j] + bav[j]);
            float g  = 1.f / (1.f + __expf(-(a2[j] + bbv[j])));
            s = fmaf(ya * g, wc[j], s);
        }
        red[ty * 8 + i][tx] = s;
    }
    __syncthreads();
    if (t < 128) {
        int r = row0 + t;
        if (r < M) {
            float s = 0.f;
#pragma unroll
            for (int x = 0; x < 16; x++) s += red[t][x];
            if (blockIdx.x == 0) s += bcp[0];
            atomicAdd(&Avec[r], s);
        }
    }
}

// ---------------- self attention ------------------------------------------
__global__ void sa_scores()
{
    int w = (blockIdx.x * 256 + threadIdx.x) >> 5;
    int lane = threadIdx.x & 31;
    if (w >= MC * MC) return;
    int i = w / MC, j = w % MC;
    const float* q = g_QKV + (size_t)i * LDQ;
    const float* k = g_QKV + (size_t)j * LDQ + DD;
    float s = 0.f;
#pragma unroll
    for (int u = 0; u < 8; u++) { int c = lane + 32 * u; s += q[c] * k[c]; }
    for (int o = 16; o > 0; o >>= 1) s += __shfl_xor_sync(0xffffffffu, s, o);
    if (lane == 0) g_SS[i * 52 + j] = s * ATT_SCALE;
}

__global__ void sa_pv()
{
    int i = blockIdx.x, d = threadIdx.x;
    float p[MC];
    float m = -1e30f;
#pragma unroll
    for (int j = 0; j < MC; j++) { p[j] = g_SS[i * 52 + j]; m = fmaxf(m, p[j]); }
    float l = 0.f;
#pragma unroll
    for (int j = 0; j < MC; j++) { p[j] = __expf(p[j] - m); l += p[j]; }
    float il = 1.f / l;
    float acc = 0.f;
#pragma unroll
    for (int j = 0; j < MC; j++)
        acc = fmaf(p[j], g_QKV[(size_t)j * LDQ + 512 + d], acc);
    g_OSC[i * DD + d] = acc * il;
}

// ---------------- cross path: P = softmax(qp.kc^T), padded to 64 ----------
__global__ __launch_bounds__(256, 2)
void cross_path()
{
    __shared__ float Qs[32][68];
    __shared__ float Ks[MC][68];
    __shared__ float P[32][56];
    int t = threadIdx.x;
    int rb = blockIdx.x * 32;
    int ip[7], jp[7];
#pragma unroll
    for (int s = 0; s < 7; s++) {
        int p = t + 256 * s;
        ip[s] = (p < 1600) ? p / MC : 0;
        jp[s] = (p < 1600) ? p % MC : 0;
    }
    float acc[7] = {0.f, 0.f, 0.f, 0.f, 0.f, 0.f, 0.f};
    for (int k0 = 0; k0 < DD; k0 += 64) {
        for (int f = t; f < 32 * 64; f += 256) {
            int r = f >> 6, cc = f & 63;
            Qs[r][cc] = g_QKV[(size_t)(MC + rb + r) * LDQ + k0 + cc];
        }
        for (int f = t; f < MC * 64; f += 256) {
            int r = f >> 6, cc = f & 63;
            Ks[r][cc] = g_QKV[(size_t)r * LDQ + DD + k0 + cc];
        }
        __syncthreads();
        for (int kk = 0; kk < 64; kk++) {
#pragma unroll
            for (int s = 0; s < 7; s++)
                acc[s] = fmaf(Qs[ip[s]][kk], Ks[jp[s]][kk], acc[s]);
        }
        __syncthreads();
    }
#pragma unroll
    for (int s = 0; s < 7; s++)
        if (t + 256 * s < 1600) P[ip[s]][jp[s]] = acc[s] * ATT_SCALE;
    __syncthreads();
    if (t < 32) {
        float m = -1e30f;
        for (int j = 0; j < MC; j++) m = fmaxf(m, P[t][j]);
        float l = 0.f;
        for (int j = 0; j < MC; j++) { float e = __expf(P[t][j] - m); P[t][j] = e; l += e; }
        float inv = 1.f / l;
        for (int j = 0; j < MC; j++) P[t][j] *= inv;
    }
    __syncthreads();
    for (int f = t; f < 32 * 64; f += 256) {
        int r = f >> 6, cc = f & 63;
        g_P[(size_t)(rb + r) * 64 + cc] = (cc < MC) ? P[r][cc] : 0.f;
    }
}

// ---------------- S2 = scale * qc @ kp^T ----------------------------------
__global__ __launch_bounds__(256, 2)
void s2k()
{
    __shared__ float Qs[MC][65];
    __shared__ float Ks[128][65];
    int t = threadIdx.x;
    int jb = blockIdx.x * 128;
    int j = t & 127, g = t >> 7;
    float acc[25];
#pragma unroll
    for (int ii = 0; ii < 25; ii++) acc[ii] = 0.f;
    for (int k0 = 0; k0 < DD; k0 += 64) {
        for (int f = t; f < MC * 64; f += 256) {
            int r = f >> 6, cc = f & 63;
            Qs[r][cc] = g_QKV[(size_t)r * LDQ + k0 + cc];
        }
        for (int f = t; f < 128 * 64; f += 256) {
            int r = f >> 6, cc = f & 63;
            Ks[r][cc] = g_QKV[(size_t)(MC + jb + r) * LDQ + DD + k0 + cc];
        }
        __syncthreads();
        for (int kk = 0; kk < 64; kk++) {
            float kvv = Ks[j][kk];
#pragma unroll
            for (int ii = 0; ii < 25; ii++)
                acc[ii] = fmaf(Qs[g * 25 + ii][kk], kvv, acc[ii]);
        }
        __syncthreads();
    }
#pragma unroll
    for (int ii = 0; ii < 25; ii++)
        g_S2[(size_t)(g * 25 + ii) * NPATH + jb + j] = acc[ii] * ATT_SCALE;
}

// ---------------- row max / inv-sumexp of S2 ------------------------------
__global__ void s2stats()
{
    __shared__ float sb[8];
    int row = blockIdx.x, t = threadIdx.x;
    const float* S = g_S2 + (size_t)row * NPATH;
    float m = -1e30f;
    for (int j = t; j < NPATH; j += 256) m = fmaxf(m, S[j]);
    for (int o = 16; o > 0; o >>= 1) m = fmaxf(m, __shfl_xor_sync(0xffffffffu, m, o));
    if ((t & 31) == 0) sb[t >> 5] = m;
    __syncthreads();
    if (t == 0) { float mm = sb[0]; for (int w = 1; w < 8; w++) mm = fmaxf(mm, sb[w]); sb[0] = mm; }
    __syncthreads();
    m = sb[0];
    __syncthreads();
    float l = 0.f;
    for (int j = t; j < NPATH; j += 256) l += __expf(S[j] - m);
    for (int o = 16; o > 0; o >>= 1) l += __shfl_xor_sync(0xffffffffu, l, o);
    if ((t & 31) == 0) sb[t >> 5] = l;
    __syncthreads();
    if (t == 0) {
        float s = 0.f; for (int w = 0; w < 8; w++) s += sb[w];
        g_rowM[row] = m; g_rowIL[row] = 1.f / s;
    }
}

// ---------------- OCC += softmax(S2) @ vp ---------------------------------
__global__ __launch_bounds__(256, 2)
void pvk()
{
    __shared__ float Ps[MC][33];
    int t = threadIdx.x;
    int d = t;
    int jb = blockIdx.x * 512;
    float acc[MC];
#pragma unroll
    for (int i = 0; i < MC; i++) acc[i] = 0.f;
    for (int jc = 0; jc < 512; jc += 32) {
        for (int f = t; f < MC * 32; f += 256) {
            int i = f >> 5, jj = f & 31;
            Ps[i][jj] = __expf(g_S2[(size_t)i * NPATH + jb + jc + jj] - g_rowM[i]) * g_rowIL[i];
        }
        __syncthreads();
        for (int jj = 0; jj < 32; jj++) {
            float v = g_QKV[(size_t)(MC + jb + jc + jj) * LDQ + 512 + d];
#pragma unroll
            for (int i = 0; i < MC; i++) acc[i] = fmaf(Ps[i][jj], v, acc[i]);
        }
        __syncthreads();
    }
#pragma unroll
    for (int i = 0; i < MC; i++) atomicAdd(&g_OCC[i * DD + d], acc[i]);
}

// ---------------- softplus precompute -------------------------------------
__global__ void spk(const float* __restrict__ sl)
{
    int c = threadIdx.x;
    g_SP[c] = 1.f / log1pf(expf(sl[c]));
}

// ---------------- linear-attention feature maps ---------------------------
__global__ void linpre()
{
    int t = threadIdx.x, lane = t & 31, w = t >> 5;
    int row = blockIdx.x * 8 + w;
    const float* base = g_QKV + (size_t)(MC + row) * LDQ;
    float q[8], k[8];
    float q2 = 0.f, k2 = 0.f;
#pragma unroll
    for (int u = 0; u < 8; u++) {
        int c = lane + 32 * u;
        float isp = g_SP[c];
        float qq = (fmaxf(base[c], 0.f) + 1e-6f) * isp;
        float kk = (fmaxf(base[DD + c], 0.f) + 1e-6f) * isp;
        q[u] = qq; k[u] = kk;
        q2 += qq * qq; k2 += kk * kk;
    }
    for (int o = 16; o > 0; o >>= 1) {
        q2 += __shfl_xor_sync(0xffffffffu, q2, o);
        k2 += __shfl_xor_sync(0xffffffffu, k2, o);
    }
    float qn = sqrtf(q2), kn = sqrtf(k2);
    float q6 = 0.f, k6 = 0.f;
#pragma unroll
    for (int u = 0; u < 8; u++) {
        float q3 = q[u] * q[u] * q[u]; q[u] = q3; q6 += q3 * q3;
        float k3 = k[u] * k[u] * k[u]; k[u] = k3; k6 += k3 * k3;
    }
    for (int o = 16; o > 0; o >>= 1) {
        q6 += __shfl_xor_sync(0xffffffffu, q6, o);
        k6 += __shfl_xor_sync(0xffffffffu, k6, o);
    }
    float qs = qn * rsqrtf(q6), ks = kn * rsqrtf(k6);
#pragma unroll
    for (int u = 0; u < 8; u++) {
        int c = lane + 32 * u;
        g_QL[(size_t)row * DD + c] = q[u] * qs;
        g_KL[(size_t)row * DD + c] = k[u] * ks;
    }
}

__global__ void ksumk()
{
    int c = threadIdx.x;
    int rb = blockIdx.x * 256;
    float s = 0.f;
    for (int r = 0; r < 256; r++) s += g_KL[(size_t)(rb + r) * DD + c];
    atomicAdd(&g_KSUM[c], s);
}

// ---------------- kv = kl^T @ vp (f32x2, 128x128 tiles, double-buffered) --
#define KV_COMPUTE(BUF)                                                      \
    _Pragma("unroll")                                                        \
    for (int jj = 0; jj < 16; jj++) {                                        \
        float a[8];                                                          \
        *(float4*)&a[0] = *(const float4*)&Ks[BUF][jj][ty * 8];              \
        *(float4*)&a[4] = *(const float4*)&Ks[BUF][jj][ty * 8 + 4];          \
        uint64_t bp[4];                                                      \
        bp[0] = *(const uint64_t*)&Vs[BUF][jj][tx * 8];                      \
        bp[1] = *(const uint64_t*)&Vs[BUF][jj][tx * 8 + 2];                  \
        bp[2] = *(const uint64_t*)&Vs[BUF][jj][tx * 8 + 4];                  \
        bp[3] = *(const uint64_t*)&Vs[BUF][jj][tx * 8 + 6];                  \
        _Pragma("unroll")                                                    \
        for (int uu = 0; uu < 8; uu++) {                                     \
            uint64_t aa = splat2(a[uu]);                                     \
            _Pragma("unroll")                                                \
            for (int vv = 0; vv < 4; vv++) fma2(acc[uu][vv], aa, bp[vv]);    \
        }                                                                    \
    }

__global__ __launch_bounds__(256, 2)
void kvk()
{
    __shared__ float Ks[2][16][128];
    __shared__ float Vs[2][16][128];
    int t = threadIdx.x;
    int c0 = blockIdx.x * 128, d0 = blockIdx.y * 128;
    int jb = blockIdx.z * 2048;
    int tx = t & 15, ty = t >> 4;
    int lr = t >> 4, lc = (t & 15) * 8;
    const float* Kp = g_KL + (size_t)(jb + lr) * DD + c0 + lc;
    const float* Vp = g_QKV + (size_t)(MC + jb + lr) * LDQ + 512 + d0 + lc;
    uint64_t acc[8][4];
#pragma unroll
    for (int uu = 0; uu < 8; uu++)
#pragma unroll
        for (int vv = 0; vv < 4; vv++) acc[uu][vv] = 0ull;

    float4 k0v = *(const float4*)Kp, k1v = *(const float4*)(Kp + 4);
    float4 v0v = *(const float4*)Vp, v1v = *(const float4*)(Vp + 4);
    *(float4*)&Ks[0][lr][lc] = k0v; *(float4*)&Ks[0][lr][lc + 4] = k1v;
    *(float4*)&Vs[0][lr][lc] = v0v; *(float4*)&Vs[0][lr][lc + 4] = v1v;
    __syncthreads();

    int buf = 0;
    for (int jt = 16; jt < 2048; jt += 16) {
        k0v = *(const float4*)(Kp + (size_t)jt * DD);
        k1v = *(const float4*)(Kp + (size_t)jt * DD + 4);
        v0v = *(const float4*)(Vp + (size_t)jt * LDQ);
        v1v = *(const float4*)(Vp + (size_t)jt * LDQ + 4);
        KV_COMPUTE(buf)
        int nb = buf ^ 1;
        *(float4*)&Ks[nb][lr][lc] = k0v; *(float4*)&Ks[nb][lr][lc + 4] = k1v;
        *(float4*)&Vs[nb][lr][lc] = v0v; *(float4*)&Vs[nb][lr][lc + 4] = v1v;
        __syncthreads();
        buf = nb;
    }
    KV_COMPUTE(buf)

#pragma unroll
    for (int uu = 0; uu < 8; uu++)
#pragma unroll
        for (int vv = 0; vv < 4; vv++) {
            float2 v = unpack2(acc[uu][vv]);
            atomicAdd(&g_KV[(c0 + ty * 8 + uu) * DD + d0 + tx * 8 + vv * 2], v.x);
            atomicAdd(&g_KV[(c0 + ty * 8 + uu) * DD + d0 + tx * 8 + vv * 2 + 1], v.y);
        }
}

__global__ void zfack()
{
    int t = threadIdx.x, lane = t & 31, w = t >> 5;
    int row = blockIdx.x * 8 + w;
    const float* q = g_QL + (size_t)row * DD;
    float s = 0.f;
#pragma unroll
    for (int u = 0; u < 8; u++) { int c = lane + 32 * u; s += q[c] * g_KSUM[c]; }
    for (int o = 16; o > 0; o >>= 1) s += __shfl_xor_sync(0xffffffffu, s, o);
    if (lane == 0) g_ZFAC[row] = 1.f / (s + 1e-6f);
}

// ---------------- depthwise 5x5 conv --------------------------------------
__global__ __launch_bounds__(256, 2)
void dwconv(const float* __restrict__ dwc_w, const float* __restrict__ dwc_b)
{
    int c = threadIdx.x;
    int i = blockIdx.x;
    int j0 = blockIdx.y * 64;
    float wt[25];
#pragma unroll
    for (int u = 0; u < 25; u++) wt[u] = dwc_w[c * 25 + u];
    float bias = dwc_b[c];
    const float* vp = g_QKV + 512 + c;
    float win[5][5];
#pragma unroll
    for (int di = 0; di < 5; di++) {
        int ii = i + di - 2;
#pragma unroll
        for (int dj = 0; dj < 5; dj++) {
            int h = j0 + dj - 2;
            win[di][dj] = (ii >= 0 && ii < 256 && h >= 0 && h < 256)
                        ? vp[(size_t)(ii * 256 + h) * LDQ] : 0.f;
        }
    }
    for (int jj = j0; jj < j0 + 64; jj++) {
        float s = bias;
#pragma unroll
        for (int di = 0; di < 5; di++)
#pragma unroll
            for (int dj = 0; dj < 5; dj++)
                s = fmaf(win[di][dj], wt[di * 5 + dj], s);
        g_FM[(size_t)(i * 256 + jj) * DD + c] = s;
        int h = jj + 3;
#pragma unroll
        for (int di = 0; di < 5; di++) {
#pragma unroll
            for (int dj = 0; dj < 4; dj++) win[di][dj] = win[di][dj + 1];
            int ii = i + di - 2;
            win[di][4] = (ii >= 0 && ii < 256 && h < 256)
                       ? vp[(size_t)(ii * 256 + h) * LDQ] : 0.f;
        }
    }
}

// ---------------- softmax-weighted sum over NPATH (stats + sum) -----------
__global__ void wstats(const float* __restrict__ A, int L)
{
    __shared__ float sb[8];
    int t = threadIdx.x;
    float m = -1e30f;
    for (int j = t; j < L; j += 256) m = fmaxf(m, A[j]);
    for (int o = 16; o > 0; o >>= 1) m = fmaxf(m, __shfl_xor_sync(0xffffffffu, m, o));
    if ((t & 31) == 0) sb[t >> 5] = m;
    __syncthreads();
    if (t == 0) { float mm = -1e30f; for (int w = 0; w < 8; w++) mm = fmaxf(mm, sb[w]); sb[0] = mm; }
    __syncthreads();
    m = sb[0];
    __syncthreads();
    float l = 0.f;
    for (int j = t; j < L; j += 256) l += __expf(A[j] - m);
    for (int o = 16; o > 0; o >>= 1) l += __shfl_xor_sync(0xffffffffu, l, o);
    if ((t & 31) == 0) sb[t >> 5] = l;
    __syncthreads();
    if (t == 0) {
        float s = 0.f; for (int w = 0; w < 8; w++) s += sb[w];
        g_ST[0] = m; g_ST[1] = 1.f / s;
    }
}

__global__ void wsum(const float* __restrict__ A, const float* __restrict__ X,
                     int L, int rpb, int ld, int ncols, float* __restrict__ out)
{
    int c = threadIdx.x;
    if (c >= ncols) return;
    int r0 = blockIdx.x * rpb;
    int r1 = min(r0 + rpb, L);
    float m = g_ST[0], il = g_ST[1];
    float acc = 0.f;
    for (int r = r0; r < r1; r++)
        acc = fmaf(__expf(A[r] - m), X[(size_t)r * ld + c], acc);
    atomicAdd(&out[c], acc * il);
}

// ---------------- fused softmax-weighted sum for L=50 (one block) ---------
__global__ void wsumMC(const float* __restrict__ A, const float* __restrict__ X,
                       float* __restrict__ out)
{
    __shared__ float sA[52];
    __shared__ float mi[2];
    int c = threadIdx.x;
    if (c < MC) sA[c] = A[c];
    __syncthreads();
    if (c == 0) {
        float m = -1e30f;
        for (int j = 0; j < MC; j++) m = fmaxf(m, sA[j]);
        float l = 0.f;
        for (int j = 0; j < MC; j++) l += __expf(sA[j] - m);
        mi[0] = m; mi[1] = 1.f / l;
    }
    __syncthreads();
    float m = mi[0], il = mi[1];
    float acc = 0.f;
    for (int r = 0; r < MC; r++)
        acc = fmaf(__expf(sA[r] - m) * il, X[(size_t)r * DD + c], acc);
    out[c] = acc;
}

// ---------------- fused 4-stage head (one block, 256 threads) -------------
__global__ void fused_head(const float* __restrict__ h1, const float* __restrict__ h2,
                           const float* __restrict__ W1, const float* __restrict__ b1,
                           const float* __restrict__ W2x, const float* __restrict__ b2x,
                           int K2,
                           const float* __restrict__ W3a, const float* __restrict__ b3a,
                           const float* __restrict__ W3b, const float* __restrict__ b3b,
                           float* __restrict__ out)
{
    __shared__ float h1s[256], h2s[256], f[512], t1s[256];
    int c = threadIdx.x;
    h1s[c] = h1[c];
    h2s[c] = (c < K2) ? h2[c] : 0.f;
    __syncthreads();
    float s1 = b1[c];
    for (int k = 0; k < DD; k++) s1 = fmaf(h1s[k], W1[k * DD + c], s1);
    float s2 = b2x[c];
    for (int k = 0; k < K2; k++) s2 = fmaf(h2s[k], W2x[k * DD + c], s2);
    f[c] = fmaxf(s1, 0.f);
    f[256 + c] = fmaxf(s2, 0.f);
    __syncthreads();
    float s3 = b3a[c];
    for (int k = 0; k < 512; k++) s3 = fmaf(f[k], W3a[k * DD + c], s3);
    t1s[c] = fmaxf(s3, 0.f);
    __syncthreads();
    float s4 = b3b[c];
    for (int k = 0; k < DD; k++) s4 = fmaf(t1s[k], W3b[k * DD + c], s4);
    out[c] = fmaxf(s4, 0.f);
}

// ---------------- host side ------------------------------------------------
extern "C" void kernel_launch(void* const* d_in, const int* in_sizes, int n_in,
                              void* d_out, int out_size)
{
    const float* x    = (const float*)d_in[0];
    const float* Wqkv = (const float*)d_in[1];
    const float* sl   = (const float*)d_in[2];
    const float* dwcw = (const float*)d_in[3];
    const float* dwcb = (const float*)d_in[4];
    const float* Wa   = (const float*)d_in[5];
    const float* ba   = (const float*)d_in[6];
    const float* Wb   = (const float*)d_in[7];
    const float* bb   = (const float*)d_in[8];
    const float* Wc   = (const float*)d_in[9];
    const float* bc   = (const float*)d_in[10];
    const float* W1   = (const float*)d_in[11];
    const float* b1   = (const float*)d_in[12];
    const float* W2   = (const float*)d_in[13];
    const float* b2   = (const float*)d_in[14];
    const float* W3a  = (const float*)d_in[15];
    const float* b3a  = (const float*)d_in[16];
    const float* W3b  = (const float*)d_in[17];
    const float* b3b  = (const float*)d_in[18];
    const float* Wf   = (const float*)d_in[19];
    const float* bf   = (const float*)d_in[20];
    float* dout = (float*)d_out;

    float *QKV, *QL, *KV, *ZFAC, *FM, *TMP, *OCC, *OSC, *P;
    float *Acc, *Acp, *Asc, *Asp, *H4;
    float *Wfa, *Wfb, *WfW2, *bfa, *bfb, *b2p, *VaP, *VbP, *VW2;
    cudaGetSymbolAddress((void**)&QKV, g_QKV);
    cudaGetSymbolAddress((void**)&QL,  g_QL);
    cudaGetSymbolAddress((void**)&KV,  g_KV);
    cudaGetSymbolAddress((void**)&ZFAC,g_ZFAC);
    cudaGetSymbolAddress((void**)&FM,  g_FM);
    cudaGetSymbolAddress((void**)&TMP, g_TMP);
    cudaGetSymbolAddress((void**)&OCC, g_OCC);
    cudaGetSymbolAddress((void**)&OSC, g_OSC);
    cudaGetSymbolAddress((void**)&P,   g_P);
    cudaGetSymbolAddress((void**)&Acc, g_Acc);
    cudaGetSymbolAddress((void**)&Acp, g_Acp);
    cudaGetSymbolAddress((void**)&Asc, g_Asc);
    cudaGetSymbolAddress((void**)&Asp, g_Asp);
    cudaGetSymbolAddress((void**)&H4,  g_H4);
    cudaGetSymbolAddress((void**)&Wfa, g_Wfa);
    cudaGetSymbolAddress((void**)&Wfb, g_Wfb);
    cudaGetSymbolAddress((void**)&WfW2,g_WfW2);
    cudaGetSymbolAddress((void**)&bfa, g_bfa);
    cudaGetSymbolAddress((void**)&bfb, g_bfb);
    cudaGetSymbolAddress((void**)&b2p, g_b2p);
    cudaGetSymbolAddress((void**)&VaP, g_VaP);
    cudaGetSymbolAddress((void**)&VbP, g_VbP);
    cudaGetSymbolAddress((void**)&VW2, g_VW2);

    zerok<<<256, 256>>>();                                                   // 1
    spk<<<1, 256>>>(sl);                                                     // 2
    sgemm_small<<<dim3(4, 4), 256>>>(Wf, DD, Wa, DD, Wfa, DD, DD, DD);       // 3
    sgemm_small<<<dim3(4, 4), 256>>>(Wf, DD, Wb, DD, Wfb, DD, DD, DD);       // 4

    // qkv = x @ W_qkv  — launch 5
    sgemm_db<<<dim3(6, 513), 256>>>(x, DD, Wqkv, 3 * DD, QKV, LDQ,
                                    NTOK, DD, nullptr, nullptr, nullptr, 0);

    sgemm_small<<<dim3(4, 4), 256>>>(Wf, DD, W2, DD, WfW2, DD, DD, DD);      // 6
    biasfold<<<1, 256>>>(ba, bf, Wa, bfa);
    biasfold<<<1, 256>>>(bb, bf, Wb, bfb);
    biasfold<<<1, 256>>>(b2, bf, W2, b2p);
    sgemm_small<<<dim3(4, 1), 256>>>(QKV + 512, LDQ, Wa, DD, VaP, DD, MC, DD);
    sgemm_small<<<dim3(4, 1), 256>>>(QKV + 512, LDQ, Wb, DD, VbP, DD, MC, DD);
    sgemm_small<<<dim3(4, 1), 256>>>(QKV + 512, LDQ, W2, DD, VW2, DD, MC, DD);

    sa_scores<<<313, 256>>>();
    sa_pv<<<50, 256>>>();
    cross_path<<<2048, 256>>>();
    s2k<<<512, 256>>>();
    s2stats<<<50, 256>>>();
    pvk<<<128, 256>>>();
    linpre<<<8192, 256>>>();
    ksumk<<<256, 256>>>();
    kvk<<<dim3(2, 2, 32), 256>>>();
    zfack<<<8192, 256>>>();
    dwconv<<<dim3(256, 4), 256>>>(dwcw, dwcb);

    // TMP = zfac .* (ql @ kv) + fm
    sgemm_db<<<dim3(2, 512), 256>>>(QL, DD, KV, DD, TMP, DD,
                                    NPATH, DD, nullptr, ZFAC, FM, DD);

    // gated row scalars
    dualgated<<<dim3(4, 1),   256>>>(OCC, DD, MC,    DD, Wa,  ba,  Wb,  bb,  Wc, bc, Acc);
    dualgated<<<dim3(4, 1),   256>>>(OSC, DD, MC,    DD, Wa,  ba,  Wb,  bb,  Wc, bc, Asc);
    dualgated<<<dim3(4, 512), 256>>>(P,   64, NPATH, 64, VaP, ba,  VbP, bb,  Wc, bc, Acp);
    dualgated<<<dim3(4, 512), 256>>>(TMP, DD, NPATH, DD, Wfa, bfa, Wfb, bfb, Wc, bc, Asp);

    // fusion_cross
    wsumMC<<<1, 256>>>(Acc, OCC, H4 + 0);
    wstats<<<1, 256>>>(Acp, NPATH);
    wsum<<<128, 256>>>(Acp, P, NPATH, 512, 64, 64, H4 + 256);
    fused_head<<<1, 256>>>(H4 + 0, H4 + 256, W1, b1, VW2, b2, 64,
                           W3a, b3a, W3b, b3b, dout + 0);

    // fusion_self
    wsumMC<<<1, 256>>>(Asc, OSC, H4 + 512);
    wstats<<<1, 256>>>(Asp, NPATH);
    wsum<<<128, 256>>>(Asp, TMP, NPATH, 512, DD, DD, H4 + 768);
    fused_head<<<1, 256>>>(H4 + 512, H4 + 768, W1, b1, WfW2, b2p, DD,
                           W3a, b3a, W3b, b3b, dout + DD);
}

// round 12
// speedup vs baseline: 1.1334x; 1.1334x over previous
#include <cuda_runtime.h>
#include <cuda_bf16.h>
#include <math.h>
#include <stdint.h>

#define DD 256
#define MC 50
#define NPATH 65536
#define NTOK 65586
#define LDQ 768
#define ATT_SCALE 0.0625f

// ---------------- scratch (device globals; no allocation allowed) ----------
__device__ float g_QKV[(size_t)NTOK * LDQ];
__device__ float g_S2[(size_t)MC * NPATH];
__device__ float g_P[(size_t)NPATH * 64];
__device__ float g_OCC[MC * DD];
__device__ float g_OSC[MC * DD];
__device__ float g_SS[MC * 52];
__device__ float g_QL[(size_t)NPATH * DD];
__device__ float g_KL[(size_t)NPATH * DD];
__device__ float g_KSUM[DD];
__device__ float g_KV[DD * DD];
__device__ float g_ZFAC[NPATH];
__device__ float g_FM[(size_t)NPATH * DD];
__device__ float g_TMP[(size_t)NPATH * DD];
__device__ float g_G[(size_t)NPATH * 512];
__device__ float g_Acc[MC], g_Asc[MC];
__device__ float g_Acp[NPATH], g_Asp[NPATH];
__device__ float g_rowM[MC], g_rowIL[MC];
__device__ float g_ST[2];
__device__ float g_SP[DD];
__device__ float g_H4[4 * DD];
__device__ float g_Wfa[DD * DD], g_Wfb[DD * DD], g_WfW2[DD * DD];
__device__ float g_bfa[DD], g_bfb[DD], g_b2p[DD];
__device__ float g_VaP[64 * DD], g_VbP[64 * DD], g_VW2[64 * DD];
// bf16 transposed weights [N][K], hi/lo split
__device__ __nv_bfloat16 g_BtQh[768 * 256], g_BtQl[768 * 256];
__device__ __nv_bfloat16 g_BtKVh[256 * 256], g_BtKVl[256 * 256];
__device__ __nv_bfloat16 g_BtWh[512 * 256], g_BtWl[512 * 256];
__device__ __nv_bfloat16 g_Bt2h[512 * 64], g_Bt2l[512 * 64];

// ---------------- zero accumulators ---------------------------------------
__global__ void zerok() {
    int id = blockIdx.x * 256 + threadIdx.x;
    if (id < NPATH) { g_Acp[id] = 0.f; g_Asp[id] = 0.f; }
    if (id < MC * DD) g_OCC[id] = 0.f;
    if (id < DD * DD) g_KV[id] = 0.f;
    if (id < DD) g_KSUM[id] = 0.f;
    if (id < MC) { g_Acc[id] = 0.f; g_Asc[id] = 0.f; }
    if (id < 4 * DD) g_H4[id] = 0.f;
    if (id < 64 * DD) { g_VaP[id] = 0.f; g_VbP[id] = 0.f; g_VW2[id] = 0.f; }
}

// ---------------- B transpose + bf16 hi/lo split ---------------------------
__global__ void btconv(const float* __restrict__ B, int ldb, int K, int N,
                       __nv_bfloat16* __restrict__ Bth, __nv_bfloat16* __restrict__ Btl)
{
    int id = blockIdx.x * 256 + threadIdx.x;
    if (id >= K * N) return;
    int n = id / K, k = id % K;
    float v = B[(size_t)k * ldb + n];
    __nv_bfloat16 h = __float2bfloat16(v);
    __nv_bfloat16 l = __float2bfloat16(v - __bfloat162float(h));
    Bth[(size_t)n * K + k] = h;
    Btl[(size_t)n * K + k] = l;
}

// ---------------- bf16 split tensor GEMM, double-buffered ------------------
// C = rowscale.*(A@Bt^T) + bias + addend. A fp32 [M,K]; Bt bf16 [N][K] hi/lo.
// Block 128x128, 8 warps (4m x 2n), warp 32x64, K chunks of 16.
__device__ __forceinline__ void mma_bf16(float* d, const uint32_t* a, const uint32_t* b)
{
    asm volatile(
        "mma.sync.aligned.m16n8k16.row.col.f32.bf16.bf16.f32 "
        "{%0,%1,%2,%3}, {%4,%5,%6,%7}, {%8,%9}, {%0,%1,%2,%3};"
        : "+f"(d[0]), "+f"(d[1]), "+f"(d[2]), "+f"(d[3])
        : "r"(a[0]), "r"(a[1]), "r"(a[2]), "r"(a[3]), "r"(b[0]), "r"(b[1]));
}

#define TCOMP(B)                                                             \
    {                                                                        \
        uint32_t ahi[2][4], alo[2][4];                                       \
        _Pragma("unroll")                                                    \
        for (int mf = 0; mf < 2; mf++) {                                     \
            int r = wm + mf * 16 + lr;                                       \
            ahi[mf][0] = Ah[B][r][lc];     ahi[mf][1] = Ah[B][r + 8][lc];    \
            ahi[mf][2] = Ah[B][r][lc + 4]; ahi[mf][3] = Ah[B][r + 8][lc + 4];\
            alo[mf][0] = Al[B][r][lc];     alo[mf][1] = Al[B][r + 8][lc];    \
            alo[mf][2] = Al[B][r][lc + 4]; alo[mf][3] = Al[B][r + 8][lc + 4];\
        }                                                                    \
        _Pragma("unroll")                                                    \
        for (int nf = 0; nf < 8; nf++) {                                     \
            int n = wn + nf * 8 + lr;                                        \
            uint32_t bhv[2], blv[2];                                         \
            bhv[0] = Bh[B][n][lc]; bhv[1] = Bh[B][n][lc + 4];                \
            blv[0] = Bl[B][n][lc]; blv[1] = Bl[B][n][lc + 4];                \
            _Pragma("unroll")                                                \
            for (int mf = 0; mf < 2; mf++) {                                 \
                mma_bf16(acc[mf][nf], ahi[mf], bhv);                         \
                mma_bf16(acc[mf][nf], ahi[mf], blv);                         \
                mma_bf16(acc[mf][nf], alo[mf], bhv);                         \
            }                                                                \
        }                                                                    \
    }

#define TLOADG(k0)                                                           \
    _Pragma("unroll")                                                        \
    for (int s = 0; s < 4; s++) {                                            \
        av[s] = (row0 + rr[s] < M)                                           \
              ? *(const float2*)(A + (size_t)(row0 + rr[s]) * lda + (k0) + kp[s] * 2) \
              : make_float2(0.f, 0.f);                                       \
        size_t bo = (size_t)(col0 + rr[s]) * K + (k0) + kp[s] * 2;           \
        bhp[s] = *(const uint32_t*)(Bth + bo);                               \
        blp[s] = *(const uint32_t*)(Btl + bo);                               \
    }

#define TSTORE(B)                                                            \
    _Pragma("unroll")                                                        \
    for (int s = 0; s < 4; s++) {                                            \
        __nv_bfloat16 h0 = __float2bfloat16(av[s].x);                        \
        __nv_bfloat16 l0 = __float2bfloat16(av[s].x - __bfloat162float(h0)); \
        __nv_bfloat16 h1 = __float2bfloat16(av[s].y);                        \
        __nv_bfloat16 l1 = __float2bfloat16(av[s].y - __bfloat162float(h1)); \
        Ah[B][rr[s]][kp[s]] = (uint32_t)__bfloat16_as_ushort(h0) |           \
                              ((uint32_t)__bfloat16_as_ushort(h1) << 16);    \
        Al[B][rr[s]][kp[s]] = (uint32_t)__bfloat16_as_ushort(l0) |           \
                              ((uint32_t)__bfloat16_as_ushort(l1) << 16);    \
        Bh[B][rr[s]][kp[s]] = bhp[s];                                        \
        Bl[B][rr[s]][kp[s]] = blp[s];                                        \
    }

__global__ __launch_bounds__(256, 2)
void tmma2(const float* __restrict__ A, int lda,
           const __nv_bfloat16* __restrict__ Bth,
           const __nv_bfloat16* __restrict__ Btl,
           int M, int K, float* __restrict__ C, int ldc,
           const float* __restrict__ bias,
           const float* __restrict__ rowscale,
           const float* __restrict__ addend, int addld)
{
    __shared__ uint32_t Ah[2][128][10], Al[2][128][10];
    __shared__ uint32_t Bh[2][128][10], Bl[2][128][10];
    const int t = threadIdx.x;
    const int lane = t & 31, wid = t >> 5;
    const int wm = (wid & 3) * 32, wn = (wid >> 2) * 64;
    const int row0 = blockIdx.y * 128, col0 = blockIdx.x * 128;
    const int lr = lane >> 2, lc = lane & 3;
    int rr[4], kp[4];
#pragma unroll
    for (int s = 0; s < 4; s++) { int idx = s * 256 + t; rr[s] = idx >> 3; kp[s] = idx & 7; }

    float acc[2][8][4];
#pragma unroll
    for (int mf = 0; mf < 2; mf++)
#pragma unroll
        for (int nf = 0; nf < 8; nf++)
#pragma unroll
            for (int u = 0; u < 4; u++) acc[mf][nf][u] = 0.f;

    float2 av[4]; uint32_t bhp[4], blp[4];
    TLOADG(0)
    TSTORE(0)
    __syncthreads();

    const int nch = K >> 4;
    int buf = 0;
    for (int ch = 1; ch < nch; ch++) {
        TLOADG(ch << 4)
        TCOMP(buf)
        TSTORE(buf ^ 1)
        __syncthreads();
        buf ^= 1;
    }
    TCOMP(buf)

#pragma unroll
    for (int mf = 0; mf < 2; mf++) {
        int r1 = row0 + wm + mf * 16 + lr;
        int r2 = r1 + 8;
        float rs1 = 1.f, rs2 = 1.f;
        if (rowscale) {
            if (r1 < M) rs1 = rowscale[r1];
            if (r2 < M) rs2 = rowscale[r2];
        }
#pragma unroll
        for (int nf = 0; nf < 8; nf++) {
            int c = col0 + wn + nf * 8 + lc * 2;
            float v0 = acc[mf][nf][0] * rs1, v1 = acc[mf][nf][1] * rs1;
            float v2 = acc[mf][nf][2] * rs2, v3 = acc[mf][nf][3] * rs2;
            if (bias) {
                float b0 = bias[c], b1 = bias[c + 1];
                v0 += b0; v1 += b1; v2 += b0; v3 += b1;
            }
            if (r1 < M) {
                if (addend) {
                    v0 += addend[(size_t)r1 * addld + c];
                    v1 += addend[(size_t)r1 * addld + c + 1];
                }
                C[(size_t)r1 * ldc + c] = v0;
                C[(size_t)r1 * ldc + c + 1] = v1;
            }
            if (r2 < M) {
                if (addend) {
                    v2 += addend[(size_t)r2 * addld + c];
                    v3 += addend[(size_t)r2 * addld + c + 1];
                }
                C[(size_t)r2 * ldc + c] = v2;
                C[(size_t)r2 * ldc + c + 1] = v3;
            }
        }
    }
}

// ---------------- gated reduce over G [NPATH x 512] ------------------------
__global__ void gatedred(const float* __restrict__ G,
                         const float* __restrict__ b1v, const float* __restrict__ b2v,
                         const float* __restrict__ Wc, const float* __restrict__ bcp,
                         float* __restrict__ out)
{
    int w = threadIdx.x >> 5, lane = threadIdx.x & 31;
    int r = blockIdx.x * 8 + w;
    const float* g = G + (size_t)r * 512;
    float s = 0.f;
#pragma unroll
    for (int u = 0; u < 8; u++) {
        int c = lane + 32 * u;
        float ya = __tanhf(g[c] + b1v[c]);
        float gg = 1.f / (1.f + __expf(-(g[c + 256] + b2v[c])));
        s = fmaf(ya * gg, Wc[c], s);
    }
    for (int o = 16; o > 0; o >>= 1) s += __shfl_xor_sync(0xffffffffu, s, o);
    if (lane == 0) out[r] = s + bcp[0];
}

// ---------------- small-matrix SGEMM: 64x64 tiles, 4x4 micro ---------------
__global__ __launch_bounds__(256, 4)
void sgemm_small(const float* __restrict__ A, int lda,
                 const float* __restrict__ B, int ldb,
                 float* __restrict__ C, int ldc, int M, int K)
{
    __shared__ float As[16][64];
    __shared__ float Bs[16][68];
    const int t = threadIdx.x;
    const int row0 = blockIdx.y * 64, col0 = blockIdx.x * 64;
    const int tx = t & 15, ty = t >> 4;
    const int arow = t >> 2, acol = (t & 3) * 4;
    const int brow = t >> 4, bcol = (t & 15) * 4;
    float acc[4][4];
#pragma unroll
    for (int i = 0; i < 4; i++)
#pragma unroll
        for (int j = 0; j < 4; j++) acc[i][j] = 0.f;

    for (int k0 = 0; k0 < K; k0 += 16) {
        float4 av = make_float4(0.f, 0.f, 0.f, 0.f);
        if (row0 + arow < M)
            av = *(const float4*)(A + (size_t)(row0 + arow) * lda + k0 + acol);
        As[acol + 0][arow] = av.x; As[acol + 1][arow] = av.y;
        As[acol + 2][arow] = av.z; As[acol + 3][arow] = av.w;
        *(float4*)&Bs[brow][bcol] =
            *(const float4*)(B + (size_t)(k0 + brow) * ldb + col0 + bcol);
        __syncthreads();
#pragma unroll
        for (int kk = 0; kk < 16; kk++) {
            float a[4], b[4];
            *(float4*)a = *(const float4*)&As[kk][ty * 4];
            *(float4*)b = *(const float4*)&Bs[kk][tx * 4];
#pragma unroll
            for (int i = 0; i < 4; i++)
#pragma unroll
                for (int j = 0; j < 4; j++)
                    acc[i][j] = fmaf(a[i], b[j], acc[i][j]);
        }
        __syncthreads();
    }
#pragma unroll
    for (int i = 0; i < 4; i++) {
        int r = row0 + ty * 4 + i;
        if (r >= M) continue;
#pragma unroll
        for (int j = 0; j < 4; j++)
            C[(size_t)r * ldc + col0 + tx * 4 + j] = acc[i][j];
    }
}

// ---------------- bias fold: out = base + vvec @ Wm ------------------------
__global__ void biasfold(const float* __restrict__ base, const float* __restrict__ vvec,
                         const float* __restrict__ Wm, float* __restrict__ out)
{
    int c = threadIdx.x;
    float s = base[c];
    for (int k = 0; k < DD; k++) s = fmaf(vvec[k], Wm[k * DD + c], s);
    out[c] = s;
}

// ---------------- dual-GEMM gated branch (small M only) --------------------
__global__ __launch_bounds__(256, 2)
void dualgated(const float* __restrict__ A, int lda, int M, int K,
               const float* __restrict__ W1m, const float* __restrict__ b1v,
               const float* __restrict__ W2m, const float* __restrict__ b2v,
               const float* __restrict__ Wc, const float* __restrict__ bcp,
               float* __restrict__ Avec)
{
    __shared__ float As[8][128];
    __shared__ float B1s[8][64];
    __shared__ float B2s[8][64];
    __shared__ float red[128][17];
    const int t = threadIdx.x;
    const int row0 = blockIdx.y * 128;
    const int col0 = blockIdx.x * 64;
    const int tx = t & 15, ty = t >> 4;
    const int arow = t >> 1, acol = (t & 1) * 4;

    float acc1[8][4], acc2[8][4];
#pragma unroll
    for (int i = 0; i < 8; i++)
#pragma unroll
        for (int j = 0; j < 4; j++) { acc1[i][j] = 0.f; acc2[i][j] = 0.f; }

    for (int k0 = 0; k0 < K; k0 += 8) {
        float4 av = make_float4(0.f, 0.f, 0.f, 0.f);
        if (row0 + arow < M)
            av = *(const float4*)(A + (size_t)(row0 + arow) * lda + k0 + acol);
        As[acol + 0][arow] = av.x; As[acol + 1][arow] = av.y;
        As[acol + 2][arow] = av.z; As[acol + 3][arow] = av.w;
        {
            int u = t & 127;
            int br = u >> 4, bc4 = (u & 15) * 4;
            const float* Bsel = (t < 128) ? W1m : W2m;
            float4 bv = *(const float4*)(Bsel + (size_t)(k0 + br) * DD + col0 + bc4);
            if (t < 128) *(float4*)&B1s[br][bc4] = bv;
            else         *(float4*)&B2s[br][bc4] = bv;
        }
        __syncthreads();
#pragma unroll
        for (int kk = 0; kk < 8; kk++) {
            float a[8], b1[4], b2[4];
            *(float4*)&a[0] = *(const float4*)&As[kk][ty * 8];
            *(float4*)&a[4] = *(const float4*)&As[kk][ty * 8 + 4];
            *(float4*)&b1[0] = *(const float4*)&B1s[kk][tx * 4];
            *(float4*)&b2[0] = *(const float4*)&B2s[kk][tx * 4];
#pragma unroll
            for (int i = 0; i < 8; i++)
#pragma unroll
                for (int j = 0; j < 4; j++) {
                    acc1[i][j] = fmaf(a[i], b1[j], acc1[i][j]);
                    acc2[i][j] = fmaf(a[i], b2[j], acc2[i][j]);
                }
        }
        __syncthreads();
    }
    float wc[4], bav[4], bbv[4];
#pragma unroll
    for (int j = 0; j < 4; j++) {
        int c = col0 + tx * 4 + j;
        wc[j] = Wc[c]; bav[j] = b1v[c]; bbv[j] = b2v[c];
    }
#pragma unroll
    for (int i = 0; i < 8; i++) {
        float s = 0.f;
#pragma unroll
        for (int j = 0; j < 4; j++) {
            float ya = __tanhf(acc1[i][j] + bav[j]);
            float g  = 1.f / (1.f + __expf(-(acc2[i][j] + bbv[j])));
            s = fmaf(ya * g, wc[j], s);
        }
        red[ty * 8 + i][tx] = s;
    }
    __syncthreads();
    if (t < 128) {
        int r = row0 + t;
        if (r < M) {
            float s = 0.f;
#pragma unroll
            for (int x = 0; x < 16; x++) s += red[t][x];
            if (blockIdx.x == 0) s += bcp[0];
            atomicAdd(&Avec[r], s);
        }
    }
}

// ---------------- self attention ------------------------------------------
__global__ void sa_scores()
{
    int w = (blockIdx.x * 256 + threadIdx.x) >> 5;
    int lane = threadIdx.x & 31;
    if (w >= MC * MC) return;
    int i = w / MC, j = w % MC;
    const float* q = g_QKV + (size_t)i * LDQ;
    const float* k = g_QKV + (size_t)j * LDQ + DD;
    float s = 0.f;
#pragma unroll
    for (int u = 0; u < 8; u++) { int c = lane + 32 * u; s += q[c] * k[c]; }
    for (int o = 16; o > 0; o >>= 1) s += __shfl_xor_sync(0xffffffffu, s, o);
    if (lane == 0) g_SS[i * 52 + j] = s * ATT_SCALE;
}

__global__ void sa_pv()
{
    int i = blockIdx.x, d = threadIdx.x;
    float p[MC];
    float m = -1e30f;
#pragma unroll
    for (int j = 0; j < MC; j++) { p[j] = g_SS[i * 52 + j]; m = fmaxf(m, p[j]); }
    float l = 0.f;
#pragma unroll
    for (int j = 0; j < MC; j++) { p[j] = __expf(p[j] - m); l += p[j]; }
    float il = 1.f / l;
    float acc = 0.f;
#pragma unroll
    for (int j = 0; j < MC; j++)
        acc = fmaf(p[j], g_QKV[(size_t)j * LDQ + 512 + d], acc);
    g_OSC[i * DD + d] = acc * il;
}

// ---------------- cross path: P = softmax(qp.kc^T), padded to 64 ----------
__global__ __launch_bounds__(256, 2)
void cross_path()
{
    __shared__ float Qs[32][68];
    __shared__ float Ks[MC][68];
    __shared__ float P[32][56];
    int t = threadIdx.x;
    int rb = blockIdx.x * 32;
    int ip[7], jp[7];
#pragma unroll
    for (int s = 0; s < 7; s++) {
        int p = t + 256 * s;
        ip[s] = (p < 1600) ? p / MC : 0;
        jp[s] = (p < 1600) ? p % MC : 0;
    }
    float acc[7] = {0.f, 0.f, 0.f, 0.f, 0.f, 0.f, 0.f};
    for (int k0 = 0; k0 < DD; k0 += 64) {
        for (int f = t; f < 32 * 64; f += 256) {
            int r = f >> 6, cc = f & 63;
            Qs[r][cc] = g_QKV[(size_t)(MC + rb + r) * LDQ + k0 + cc];
        }
        for (int f = t; f < MC * 64; f += 256) {
            int r = f >> 6, cc = f & 63;
            Ks[r][cc] = g_QKV[(size_t)r * LDQ + DD + k0 + cc];
        }
        __syncthreads();
        for (int kk = 0; kk < 64; kk++) {
#pragma unroll
            for (int s = 0; s < 7; s++)
                acc[s] = fmaf(Qs[ip[s]][kk], Ks[jp[s]][kk], acc[s]);
        }
        __syncthreads();
    }
#pragma unroll
    for (int s = 0; s < 7; s++)
        if (t + 256 * s < 1600) P[ip[s]][jp[s]] = acc[s] * ATT_SCALE;
    __syncthreads();
    if (t < 32) {
        float m = -1e30f;
        for (int j = 0; j < MC; j++) m = fmaxf(m, P[t][j]);
        float l = 0.f;
        for (int j = 0; j < MC; j++) { float e = __expf(P[t][j] - m); P[t][j] = e; l += e; }
        float inv = 1.f / l;
        for (int j = 0; j < MC; j++) P[t][j] *= inv;
    }
    __syncthreads();
    for (int f = t; f < 32 * 64; f += 256) {
        int r = f >> 6, cc = f & 63;
        g_P[(size_t)(rb + r) * 64 + cc] = (cc < MC) ? P[r][cc] : 0.f;
    }
}

// ---------------- S2 = scale * qc @ kp^T ----------------------------------
__global__ __launch_bounds__(256, 2)
void s2k()
{
    __shared__ float Qs[MC][65];
    __shared__ float Ks[128][65];
    int t = threadIdx.x;
    int jb = blockIdx.x * 128;
    int j = t & 127, g = t >> 7;
    float acc[25];
#pragma unroll
    for (int ii = 0; ii < 25; ii++) acc[ii] = 0.f;
    for (int k0 = 0; k0 < DD; k0 += 64) {
        for (int f = t; f < MC * 64; f += 256) {
            int r = f >> 6, cc = f & 63;
            Qs[r][cc] = g_QKV[(size_t)r * LDQ + k0 + cc];
        }
        for (int f = t; f < 128 * 64; f += 256) {
            int r = f >> 6, cc = f & 63;
            Ks[r][cc] = g_QKV[(size_t)(MC + jb + r) * LDQ + DD + k0 + cc];
        }
        __syncthreads();
        for (int kk = 0; kk < 64; kk++) {
            float kvv = Ks[j][kk];
#pragma unroll
            for (int ii = 0; ii < 25; ii++)
                acc[ii] = fmaf(Qs[g * 25 + ii][kk], kvv, acc[ii]);
        }
        __syncthreads();
    }
#pragma unroll
    for (int ii = 0; ii < 25; ii++)
        g_S2[(size_t)(g * 25 + ii) * NPATH + jb + j] = acc[ii] * ATT_SCALE;
}

// ---------------- row max / inv-sumexp of S2 ------------------------------
__global__ void s2stats()
{
    __shared__ float sb[8];
    int row = blockIdx.x, t = threadIdx.x;
    const float* S = g_S2 + (size_t)row * NPATH;
    float m = -1e30f;
    for (int j = t; j < NPATH; j += 256) m = fmaxf(m, S[j]);
    for (int o = 16; o > 0; o >>= 1) m = fmaxf(m, __shfl_xor_sync(0xffffffffu, m, o));
    if ((t & 31) == 0) sb[t >> 5] = m;
    __syncthreads();
    if (t == 0) { float mm = sb[0]; for (int w = 1; w < 8; w++) mm = fmaxf(mm, sb[w]); sb[0] = mm; }
    __syncthreads();
    m = sb[0];
    __syncthreads();
    float l = 0.f;
    for (int j = t; j < NPATH; j += 256) l += __expf(S[j] - m);
    for (int o = 16; o > 0; o >>= 1) l += __shfl_xor_sync(0xffffffffu, l, o);
    if ((t & 31) == 0) sb[t >> 5] = l;
    __syncthreads();
    if (t == 0) {
        float s = 0.f; for (int w = 0; w < 8; w++) s += sb[w];
        g_rowM[row] = m; g_rowIL[row] = 1.f / s;
    }
}

// ---------------- OCC += softmax(S2) @ vp ---------------------------------
__global__ __launch_bounds__(256, 2)
void pvk()
{
    __shared__ float Ps[MC][33];
    int t = threadIdx.x;
    int d = t;
    int jb = blockIdx.x * 512;
    float acc[MC];
#pragma unroll
    for (int i = 0; i < MC; i++) acc[i] = 0.f;
    for (int jc = 0; jc < 512; jc += 32) {
        for (int f = t; f < MC * 32; f += 256) {
            int i = f >> 5, jj = f & 31;
            Ps[i][jj] = __expf(g_S2[(size_t)i * NPATH + jb + jc + jj] - g_rowM[i]) * g_rowIL[i];
        }
        __syncthreads();
        for (int jj = 0; jj < 32; jj++) {
            float v = g_QKV[(size_t)(MC + jb + jc + jj) * LDQ + 512 + d];
#pragma unroll
            for (int i = 0; i < MC; i++) acc[i] = fmaf(Ps[i][jj], v, acc[i]);
        }
        __syncthreads();
    }
#pragma unroll
    for (int i = 0; i < MC; i++) atomicAdd(&g_OCC[i * DD + d], acc[i]);
}

// ---------------- softplus precompute -------------------------------------
__global__ void spk(const float* __restrict__ sl)
{
    int c = threadIdx.x;
    g_SP[c] = 1.f / log1pf(expf(sl[c]));
}

// ---------------- linear-attention feature maps ---------------------------
__global__ void linpre()
{
    int t = threadIdx.x, lane = t & 31, w = t >> 5;
    int row = blockIdx.x * 8 + w;
    const float* base = g_QKV + (size_t)(MC + row) * LDQ;
    float q[8], k[8];
    float q2 = 0.f, k2 = 0.f;
#pragma unroll
    for (int u = 0; u < 8; u++) {
        int c = lane + 32 * u;
        float isp = g_SP[c];
        float qq = (fmaxf(base[c], 0.f) + 1e-6f) * isp;
        float kk = (fmaxf(base[DD + c], 0.f) + 1e-6f) * isp;
        q[u] = qq; k[u] = kk;
        q2 += qq * qq; k2 += kk * kk;
    }
    for (int o = 16; o > 0; o >>= 1) {
        q2 += __shfl_xor_sync(0xffffffffu, q2, o);
        k2 += __shfl_xor_sync(0xffffffffu, k2, o);
    }
    float qn = sqrtf(q2), kn = sqrtf(k2);
    float q6 = 0.f, k6 = 0.f;
#pragma unroll
    for (int u = 0; u < 8; u++) {
        float q3 = q[u] * q[u] * q[u]; q[u] = q3; q6 += q3 * q3;
        float k3 = k[u] * k[u] * k[u]; k[u] = k3; k6 += k3 * k3;
    }
    for (int o = 16; o > 0; o >>= 1) {
        q6 += __shfl_xor_sync(0xffffffffu, q6, o);
        k6 += __shfl_xor_sync(0xffffffffu, k6, o);
    }
    float qs = qn * rsqrtf(q6), ks = kn * rsqrtf(k6);
#pragma unroll
    for (int u = 0; u < 8; u++) {
        int c = lane + 32 * u;
        g_QL[(size_t)row * DD + c] = q[u] * qs;
        g_KL[(size_t)row * DD + c] = k[u] * ks;
    }
}

__global__ void ksumk()
{
    int c = threadIdx.x;
    int rb = blockIdx.x * 256;
    float s = 0.f;
    for (int r = 0; r < 256; r++) s += g_KL[(size_t)(rb + r) * DD + c];
    atomicAdd(&g_KSUM[c], s);
}

// ---------------- kv = kl^T @ vp (128x128 tiles, double-buffered) ---------
#define KV_COMPUTE(BUF)                                                      \
    _Pragma("unroll")                                                        \
    for (int jj = 0; jj < 16; jj++) {                                        \
        float a[8], b[8];                                                    \
        *(float4*)&a[0] = *(const float4*)&Ks[BUF][jj][ty * 8];              \
        *(float4*)&a[4] = *(const float4*)&Ks[BUF][jj][ty * 8 + 4];          \
        *(float4*)&b[0] = *(const float4*)&Vs[BUF][jj][tx * 8];              \
        *(float4*)&b[4] = *(const float4*)&Vs[BUF][jj][tx * 8 + 4];          \
        _Pragma("unroll")                                                    \
        for (int uu = 0; uu < 8; uu++)                                       \
            _Pragma("unroll")                                                \
            for (int vv = 0; vv < 8; vv++)                                   \
                acc[uu][vv] = fmaf(a[uu], b[vv], acc[uu][vv]);               \
    }

__global__ __launch_bounds__(256, 2)
void kvk()
{
    __shared__ float Ks[2][16][128];
    __shared__ float Vs[2][16][128];
    int t = threadIdx.x;
    int c0 = blockIdx.x * 128, d0 = blockIdx.y * 128;
    int jb = blockIdx.z * 2048;
    int tx = t & 15, ty = t >> 4;
    int lr = t >> 4, lc = (t & 15) * 8;
    const float* Kp = g_KL + (size_t)(jb + lr) * DD + c0 + lc;
    const float* Vp = g_QKV + (size_t)(MC + jb + lr) * LDQ + 512 + d0 + lc;
    float acc[8][8];
#pragma unroll
    for (int uu = 0; uu < 8; uu++)
#pragma unroll
        for (int vv = 0; vv < 8; vv++) acc[uu][vv] = 0.f;

    float4 k0v = *(const float4*)Kp, k1v = *(const float4*)(Kp + 4);
    float4 v0v = *(const float4*)Vp, v1v = *(const float4*)(Vp + 4);
    *(float4*)&Ks[0][lr][lc] = k0v; *(float4*)&Ks[0][lr][lc + 4] = k1v;
    *(float4*)&Vs[0][lr][lc] = v0v; *(float4*)&Vs[0][lr][lc + 4] = v1v;
    __syncthreads();

    int buf = 0;
    for (int jt = 16; jt < 2048; jt += 16) {
        k0v = *(const float4*)(Kp + (size_t)jt * DD);
        k1v = *(const float4*)(Kp + (size_t)jt * DD + 4);
        v0v = *(const float4*)(Vp + (size_t)jt * LDQ);
        v1v = *(const float4*)(Vp + (size_t)jt * LDQ + 4);
        KV_COMPUTE(buf)
        int nb = buf ^ 1;
        *(float4*)&Ks[nb][lr][lc] = k0v; *(float4*)&Ks[nb][lr][lc + 4] = k1v;
        *(float4*)&Vs[nb][lr][lc] = v0v; *(float4*)&Vs[nb][lr][lc + 4] = v1v;
        __syncthreads();
        buf = nb;
    }
    KV_COMPUTE(buf)

#pragma unroll
    for (int uu = 0; uu < 8; uu++)
#pragma unroll
        for (int vv = 0; vv < 8; vv++)
            atomicAdd(&g_KV[(c0 + ty * 8 + uu) * DD + d0 + tx * 8 + vv], acc[uu][vv]);
}

__global__ void zfack()
{
    int t = threadIdx.x, lane = t & 31, w = t >> 5;
    int row = blockIdx.x * 8 + w;
    const float* q = g_QL + (size_t)row * DD;
    float s = 0.f;
#pragma unroll
    for (int u = 0; u < 8; u++) { int c = lane + 32 * u; s += q[c] * g_KSUM[c]; }
    for (int o = 16; o > 0; o >>= 1) s += __shfl_xor_sync(0xffffffffu, s, o);
    if (lane == 0) g_ZFAC[row] = 1.f / (s + 1e-6f);
}

// ---------------- depthwise 5x5 conv --------------------------------------
__global__ __launch_bounds__(256, 2)
void dwconv(const float* __restrict__ dwc_w, const float* __restrict__ dwc_b)
{
    int c = threadIdx.x;
    int i = blockIdx.x;
    int j0 = blockIdx.y * 64;
    float wt[25];
#pragma unroll
    for (int u = 0; u < 25; u++) wt[u] = dwc_w[c * 25 + u];
    float bias = dwc_b[c];
    const float* vp = g_QKV + 512 + c;
    float win[5][5];
#pragma unroll
    for (int di = 0; di < 5; di++) {
        int ii = i + di - 2;
#pragma unroll
        for (int dj = 0; dj < 5; dj++) {
            int h = j0 + dj - 2;
            win[di][dj] = (ii >= 0 && ii < 256 && h >= 0 && h < 256)
                        ? vp[(size_t)(ii * 256 + h) * LDQ] : 0.f;
        }
    }
    for (int jj = j0; jj < j0 + 64; jj++) {
        float s = bias;
#pragma unroll
        for (int di = 0; di < 5; di++)
#pragma unroll
            for (int dj = 0; dj < 5; dj++)
                s = fmaf(win[di][dj], wt[di * 5 + dj], s);
        g_FM[(size_t)(i * 256 + jj) * DD + c] = s;
        int h = jj + 3;
#pragma unroll
        for (int di = 0; di < 5; di++) {
#pragma unroll
            for (int dj = 0; dj < 4; dj++) win[di][dj] = win[di][dj + 1];
            int ii = i + di - 2;
            win[di][4] = (ii >= 0 && ii < 256 && h < 256)
                       ? vp[(size_t)(ii * 256 + h) * LDQ] : 0.f;
        }
    }
}

// ---------------- softmax-weighted sum over NPATH -------------------------
__global__ void wstats(const float* __restrict__ A, int L)
{
    __shared__ float sb[8];
    int t = threadIdx.x;
    float m = -1e30f;
    for (int j = t; j < L; j += 256) m = fmaxf(m, A[j]);
    for (int o = 16; o > 0; o >>= 1) m = fmaxf(m, __shfl_xor_sync(0xffffffffu, m, o));
    if ((t & 31) == 0) sb[t >> 5] = m;
    __syncthreads();
    if (t == 0) { float mm = -1e30f; for (int w = 0; w < 8; w++) mm = fmaxf(mm, sb[w]); sb[0] = mm; }
    __syncthreads();
    m = sb[0];
    __syncthreads();
    float l = 0.f;
    for (int j = t; j < L; j += 256) l += __expf(A[j] - m);
    for (int o = 16; o > 0; o >>= 1) l += __shfl_xor_sync(0xffffffffu, l, o);
    if ((t & 31) == 0) sb[t >> 5] = l;
    __syncthreads();
    if (t == 0) {
        float s = 0.f; for (int w = 0; w < 8; w++) s += sb[w];
        g_ST[0] = m; g_ST[1] = 1.f / s;
    }
}

__global__ void wsum(const float* __restrict__ A, const float* __restrict__ X,
                     int L, int rpb, int ld, int ncols, float* __restrict__ out)
{
    int c = threadIdx.x;
    if (c >= ncols) return;
    int r0 = blockIdx.x * rpb;
    int r1 = min(r0 + rpb, L);
    float m = g_ST[0], il = g_ST[1];
    float acc = 0.f;
    for (int r = r0; r < r1; r++)
        acc = fmaf(__expf(A[r] - m), X[(size_t)r * ld + c], acc);
    atomicAdd(&out[c], acc * il);
}

// ---------------- fused softmax-weighted sum for L=50 ---------------------
__global__ void wsumMC(const float* __restrict__ A, const float* __restrict__ X,
                       float* __restrict__ out)
{
    __shared__ float sA[52];
    __shared__ float mi[2];
    int c = threadIdx.x;
    if (c < MC) sA[c] = A[c];
    __syncthreads();
    if (c == 0) {
        float m = -1e30f;
        for (int j = 0; j < MC; j++) m = fmaxf(m, sA[j]);
        float l = 0.f;
        for (int j = 0; j < MC; j++) l += __expf(sA[j] - m);
        mi[0] = m; mi[1] = 1.f / l;
    }
    __syncthreads();
    float m = mi[0], il = mi[1];
    float acc = 0.f;
    for (int r = 0; r < MC; r++)
        acc = fmaf(__expf(sA[r] - m) * il, X[(size_t)r * DD + c], acc);
    out[c] = acc;
}

// ---------------- fused 4-stage head --------------------------------------
__global__ void fused_head(const float* __restrict__ h1, const float* __restrict__ h2,
                           const float* __restrict__ W1, const float* __restrict__ b1,
                           const float* __restrict__ W2x, const float* __restrict__ b2x,
                           int K2,
                           const float* __restrict__ W3a, const float* __restrict__ b3a,
                           const float* __restrict__ W3b, const float* __restrict__ b3b,
                           float* __restrict__ out)
{
    __shared__ float h1s[256], h2s[256], f[512], t1s[256];
    int c = threadIdx.x;
    h1s[c] = h1[c];
    h2s[c] = (c < K2) ? h2[c] : 0.f;
    __syncthreads();
    float s1 = b1[c];
    for (int k = 0; k < DD; k++) s1 = fmaf(h1s[k], W1[k * DD + c], s1);
    float s2 = b2x[c];
    for (int k = 0; k < K2; k++) s2 = fmaf(h2s[k], W2x[k * DD + c], s2);
    f[c] = fmaxf(s1, 0.f);
    f[256 + c] = fmaxf(s2, 0.f);
    __syncthreads();
    float s3 = b3a[c];
    for (int k = 0; k < 512; k++) s3 = fmaf(f[k], W3a[k * DD + c], s3);
    t1s[c] = fmaxf(s3, 0.f);
    __syncthreads();
    float s4 = b3b[c];
    for (int k = 0; k < DD; k++) s4 = fmaf(t1s[k], W3b[k * DD + c], s4);
    out[c] = fmaxf(s4, 0.f);
}

// ---------------- host side ------------------------------------------------
extern "C" void kernel_launch(void* const* d_in, const int* in_sizes, int n_in,
                              void* d_out, int out_size)
{
    const float* x    = (const float*)d_in[0];
    const float* Wqkv = (const float*)d_in[1];
    const float* sl   = (const float*)d_in[2];
    const float* dwcw = (const float*)d_in[3];
    const float* dwcb = (const float*)d_in[4];
    const float* Wa   = (const float*)d_in[5];
    const float* ba   = (const float*)d_in[6];
    const float* Wb   = (const float*)d_in[7];
    const float* bb   = (const float*)d_in[8];
    const float* Wc   = (const float*)d_in[9];
    const float* bc   = (const float*)d_in[10];
    const float* W1   = (const float*)d_in[11];
    const float* b1   = (const float*)d_in[12];
    const float* W2   = (const float*)d_in[13];
    const float* b2   = (const float*)d_in[14];
    const float* W3a  = (const float*)d_in[15];
    const float* b3a  = (const float*)d_in[16];
    const float* W3b  = (const float*)d_in[17];
    const float* b3b  = (const float*)d_in[18];
    const float* Wf   = (const float*)d_in[19];
    const float* bf   = (const float*)d_in[20];
    float* dout = (float*)d_out;

    float *QKV, *QL, *KV, *ZFAC, *FM, *TMP, *OCC, *OSC, *P, *G;
    float *Acc, *Acp, *Asc, *Asp, *H4;
    float *Wfa, *Wfb, *WfW2, *bfa, *bfb, *b2p, *VaP, *VbP, *VW2;
    __nv_bfloat16 *BtQh, *BtQl, *BtKVh, *BtKVl, *BtWh, *BtWl, *Bt2h, *Bt2l;
    cudaGetSymbolAddress((void**)&QKV, g_QKV);
    cudaGetSymbolAddress((void**)&QL,  g_QL);
    cudaGetSymbolAddress((void**)&KV,  g_KV);
    cudaGetSymbolAddress((void**)&ZFAC,g_ZFAC);
    cudaGetSymbolAddress((void**)&FM,  g_FM);
    cudaGetSymbolAddress((void**)&TMP, g_TMP);
    cudaGetSymbolAddress((void**)&OCC, g_OCC);
    cudaGetSymbolAddress((void**)&OSC, g_OSC);
    cudaGetSymbolAddress((void**)&P,   g_P);
    cudaGetSymbolAddress((void**)&G,   g_G);
    cudaGetSymbolAddress((void**)&Acc, g_Acc);
    cudaGetSymbolAddress((void**)&Acp, g_Acp);
    cudaGetSymbolAddress((void**)&Asc, g_Asc);
    cudaGetSymbolAddress((void**)&Asp, g_Asp);
    cudaGetSymbolAddress((void**)&H4,  g_H4);
    cudaGetSymbolAddress((void**)&Wfa, g_Wfa);
    cudaGetSymbolAddress((void**)&Wfb, g_Wfb);
    cudaGetSymbolAddress((void**)&WfW2,g_WfW2);
    cudaGetSymbolAddress((void**)&bfa, g_bfa);
    cudaGetSymbolAddress((void**)&bfb, g_bfb);
    cudaGetSymbolAddress((void**)&b2p, g_b2p);
    cudaGetSymbolAddress((void**)&VaP, g_VaP);
    cudaGetSymbolAddress((void**)&VbP, g_VbP);
    cudaGetSymbolAddress((void**)&VW2, g_VW2);
    cudaGetSymbolAddress((void**)&BtQh, g_BtQh);
    cudaGetSymbolAddress((void**)&BtQl, g_BtQl);
    cudaGetSymbolAddress((void**)&BtKVh, g_BtKVh);
    cudaGetSymbolAddress((void**)&BtKVl, g_BtKVl);
    cudaGetSymbolAddress((void**)&BtWh, g_BtWh);
    cudaGetSymbolAddress((void**)&BtWl, g_BtWl);
    cudaGetSymbolAddress((void**)&Bt2h, g_Bt2h);
    cudaGetSymbolAddress((void**)&Bt2l, g_Bt2l);

    zerok<<<256, 256>>>();                                                   // 1
    spk<<<1, 256>>>(sl);                                                     // 2
    btconv<<<768, 256>>>(Wqkv, 768, 256, 768, BtQh, BtQl);                   // 3
    sgemm_small<<<dim3(4, 4), 256>>>(Wf, DD, Wa, DD, Wfa, DD, DD, DD);       // 4
    sgemm_small<<<dim3(4, 4), 256>>>(Wf, DD, Wb, DD, Wfb, DD, DD, DD);       // 5

    // qkv = x @ W_qkv — launch 6 (profiled)
    tmma2<<<dim3(6, 513), 256>>>(x, DD, BtQh, BtQl, NTOK, DD, QKV, LDQ,
                                 nullptr, nullptr, nullptr, 0);

    sgemm_small<<<dim3(4, 4), 256>>>(Wf, DD, W2, DD, WfW2, DD, DD, DD);
    biasfold<<<1, 256>>>(ba, bf, Wa, bfa);
    biasfold<<<1, 256>>>(bb, bf, Wb, bfb);
    biasfold<<<1, 256>>>(b2, bf, W2, b2p);
    btconv<<<256, 256>>>(Wfa, 256, 256, 256, BtWh, BtWl);
    btconv<<<256, 256>>>(Wfb, 256, 256, 256, BtWh + 256 * 256, BtWl + 256 * 256);
    sgemm_small<<<dim3(4, 1), 256>>>(QKV + 512, LDQ, Wa, DD, VaP, DD, MC, DD);
    sgemm_small<<<dim3(4, 1), 256>>>(QKV + 512, LDQ, Wb, DD, VbP, DD, MC, DD);
    sgemm_small<<<dim3(4, 1), 256>>>(QKV + 512, LDQ, W2, DD, VW2, DD, MC, DD);
    btconv<<<64, 256>>>(VaP, 256, 64, 256, Bt2h, Bt2l);
    btconv<<<64, 256>>>(VbP, 256, 64, 256, Bt2h + 256 * 64, Bt2l + 256 * 64);

    sa_scores<<<313, 256>>>();
    sa_pv<<<50, 256>>>();
    cross_path<<<2048, 256>>>();
    s2k<<<512, 256>>>();
    s2stats<<<50, 256>>>();
    pvk<<<128, 256>>>();
    linpre<<<8192, 256>>>();
    ksumk<<<256, 256>>>();
    kvk<<<dim3(2, 2, 32), 256>>>();
    zfack<<<8192, 256>>>();
    dwconv<<<dim3(256, 4), 256>>>(dwcw, dwcb);

    // TMP = zfac .* (ql @ kv) + fm
    btconv<<<256, 256>>>(KV, 256, 256, 256, BtKVh, BtKVl);
    tmma2<<<dim3(2, 512), 256>>>(QL, DD, BtKVh, BtKVl, NPATH, DD, TMP, DD,
                                 nullptr, ZFAC, FM, DD);

    // small gated (SIMT)
    dualgated<<<dim3(4, 1), 256>>>(OCC, DD, MC, DD, Wa, ba, Wb, bb, Wc, bc, Acc);
    dualgated<<<dim3(4, 1), 256>>>(OSC, DD, MC, DD, Wa, ba, Wb, bb, Wc, bc, Asc);

    // Acp: G = P @ [VaP|VbP], gated reduce
    tmma2<<<dim3(4, 512), 256>>>(P, 64, Bt2h, Bt2l, NPATH, 64, G, 512,
                                 nullptr, nullptr, nullptr, 0);
    gatedred<<<8192, 256>>>(G, ba, bb, Wc, bc, Acp);

    // Asp: G = TMP @ [Wfa|Wfb], gated reduce
    tmma2<<<dim3(4, 512), 256>>>(TMP, DD, BtWh, BtWl, NPATH, DD, G, 512,
                                 nullptr, nullptr, nullptr, 0);
    gatedred<<<8192, 256>>>(G, bfa, bfb, Wc, bc, Asp);

    // fusion_cross
    wsumMC<<<1, 256>>>(Acc, OCC, H4 + 0);
    wstats<<<1, 256>>>(Acp, NPATH);
    wsum<<<128, 256>>>(Acp, P, NPATH, 512, 64, 64, H4 + 256);
    fused_head<<<1, 256>>>(H4 + 0, H4 + 256, W1, b1, VW2, b2, 64,
                           W3a, b3a, W3b, b3b, dout + 0);

    // fusion_self
    wsumMC<<<1, 256>>>(Asc, OSC, H4 + 512);
    wstats<<<1, 256>>>(Asp, NPATH);
    wsum<<<128, 256>>>(Asp, TMP, NPATH, 512, DD, DD, H4 + 768);
    fused_head<<<1, 256>>>(H4 + 512, H4 + 768, W1, b1, WfW2, b2p, DD,
                           W3a, b3a, W3b, b3b, dout + DD);
}